// round 9
// baseline (speedup 1.0000x reference)
#include <cuda_runtime.h>
#include <math.h>
#include <stdint.h>

#define Bn 64
#define Ln 2048
#define Hn 128
#define Vn 32000

// ---------------- scratch (static device globals; no runtime allocation) ----
__device__ float  g_ff1[(size_t)Vn * 256];
__device__ float  g_x  [(size_t)Vn * Hn];
__device__ float  g_hn [(size_t)Vn * Hn];
__device__ float  g_kt [(size_t)Vn * Hn];
__device__ float  g_kn [(size_t)Vn * Hn];
__device__ float2 g_meta[Vn];            // (norm, ||kn||^2)
__device__ float  g_read[Bn * Hn];
__device__ float  g_tmp [Bn * Hn];
__device__ float  g_zero[256];           // zero-initialized: dummy bias

// packed fp32x2 FMA (Blackwell FFMA2 — only reachable via PTX fma.rn.f32x2)
__device__ __forceinline__ float2 ffma2(float2 a, float2 b, float2 c) {
    float2 d;
    asm("fma.rn.f32x2 %0, %1, %2, %3;"
        : "=l"(reinterpret_cast<unsigned long long&>(d))
        : "l"(reinterpret_cast<unsigned long long&>(a)),
          "l"(reinterpret_cast<unsigned long long&>(b)),
          "l"(reinterpret_cast<unsigned long long&>(c)));
    return d;
}

// async global->shared copies (no register landing; completion via groups)
__device__ __forceinline__ void cp_async16(void* sdst, const void* gsrc) {
    uint32_t sa = (uint32_t)__cvta_generic_to_shared(sdst);
    asm volatile("cp.async.cg.shared.global [%0], [%1], 16;" :: "r"(sa), "l"(gsrc));
}
__device__ __forceinline__ void cp_async8(void* sdst, const void* gsrc) {
    uint32_t sa = (uint32_t)__cvta_generic_to_shared(sdst);
    asm volatile("cp.async.ca.shared.global [%0], [%1], 8;" :: "r"(sa), "l"(gsrc));
}

// ---------------- generic fp32 GEMM (unchanged) ------------------------------
template <bool RELU, bool RESID>
__global__ void __launch_bounds__(256, 2) sgemm_tn(
    const float* __restrict__ A, const float* __restrict__ Bm,
    const float* __restrict__ bias, const float* __restrict__ resid,
    float* __restrict__ C, int Nn, int K)
{
    __shared__ float As[32][132];
    __shared__ float Bs[32][132];
    const int m0 = blockIdx.x * 128;
    const int n0 = blockIdx.y * 128;
    const int tid = threadIdx.x;
    const int tx = tid & 15;
    const int ty = tid >> 4;
    const int lrow = tid >> 3;       // 0..31
    const int lk   = (tid & 7) * 4;  // 0..28

    float2 acc2[8][4];
#pragma unroll
    for (int i = 0; i < 8; ++i)
#pragma unroll
        for (int j = 0; j < 4; ++j) acc2[i][j] = make_float2(0.f, 0.f);

    for (int k0 = 0; k0 < K; k0 += 32) {
#pragma unroll
        for (int p = 0; p < 4; ++p) {
            int row = lrow + p * 32;
            float4 av = *(const float4*)&A [(size_t)(m0 + row) * K + k0 + lk];
            As[lk + 0][row] = av.x; As[lk + 1][row] = av.y;
            As[lk + 2][row] = av.z; As[lk + 3][row] = av.w;
            float4 bv = *(const float4*)&Bm[(size_t)(n0 + row) * K + k0 + lk];
            Bs[lk + 0][row] = bv.x; Bs[lk + 1][row] = bv.y;
            Bs[lk + 2][row] = bv.z; Bs[lk + 3][row] = bv.w;
        }
        __syncthreads();
#pragma unroll 8
        for (int kk = 0; kk < 32; ++kk) {
            float4 a0 = *(const float4*)&As[kk][ty * 8];
            float4 a1 = *(const float4*)&As[kk][ty * 8 + 4];
            float4 b0 = *(const float4*)&Bs[kk][tx * 8];
            float4 b1 = *(const float4*)&Bs[kk][tx * 8 + 4];
            float a[8] = {a0.x, a0.y, a0.z, a0.w, a1.x, a1.y, a1.z, a1.w};
            float2 bb[4] = {make_float2(b0.x, b0.y), make_float2(b0.z, b0.w),
                            make_float2(b1.x, b1.y), make_float2(b1.z, b1.w)};
#pragma unroll
            for (int i = 0; i < 8; ++i) {
                float2 ai = make_float2(a[i], a[i]);
#pragma unroll
                for (int j = 0; j < 4; ++j)
                    acc2[i][j] = ffma2(ai, bb[j], acc2[i][j]);
            }
        }
        __syncthreads();
    }

#pragma unroll
    for (int i = 0; i < 8; ++i) {
        const int m = m0 + ty * 8 + i;
#pragma unroll
        for (int j = 0; j < 4; ++j) {
            const int n = n0 + tx * 8 + j * 2;
            float vx = acc2[i][j].x + bias[n];
            float vy = acc2[i][j].y + bias[n + 1];
            if (RELU) { vx = fmaxf(vx, 0.f); vy = fmaxf(vy, 0.f); }
            if (RESID) {
                vx += resid[(size_t)m * Nn + n];
                vy += resid[(size_t)m * Nn + n + 1];
            }
            C[(size_t)m * Nn + n]     = vx;
            C[(size_t)m * Nn + n + 1] = vy;
        }
    }
}

// ---------------- LayerNorm: one warp per row of 128 -------------------------
__global__ void __launch_bounds__(256) ln_kernel(
    const float* __restrict__ g, const float* __restrict__ bparm)
{
    const int lane = threadIdx.x & 31;
    const int row  = blockIdx.x * 8 + (threadIdx.x >> 5);
    float4 v = ((const float4*)(g_x + (size_t)row * Hn))[lane];
    float s = (v.x + v.y) + (v.z + v.w);
#pragma unroll
    for (int d = 16; d; d >>= 1) s += __shfl_xor_sync(0xffffffffu, s, d);
    const float mu = s * (1.0f / 128.0f);
    float dx = v.x - mu, dy = v.y - mu, dz = v.z - mu, dw = v.w - mu;
    float q = (dx * dx + dy * dy) + (dz * dz + dw * dw);
#pragma unroll
    for (int d = 16; d; d >>= 1) q += __shfl_xor_sync(0xffffffffu, q, d);
    const float rstd = rsqrtf(q * (1.0f / 128.0f) + 1e-5f);
    float4 gg = ((const float4*)g)[lane];
    float4 bb = ((const float4*)bparm)[lane];
    float4 o;
    o.x = fmaf(dx * rstd, gg.x, bb.x);
    o.y = fmaf(dy * rstd, gg.y, bb.y);
    o.z = fmaf(dz * rstd, gg.z, bb.z);
    o.w = fmaf(dw * rstd, gg.w, bb.w);
    ((float4*)(g_hn + (size_t)row * Hn))[lane] = o;
}

// ---------------- row normalize k-table: kn + packed meta --------------------
__global__ void __launch_bounds__(256) norm_kernel()
{
    const int lane = threadIdx.x & 31;
    const int row  = blockIdx.x * 8 + (threadIdx.x >> 5);
    float4 v = ((const float4*)(g_kt + (size_t)row * Hn))[lane];
    float q = (v.x * v.x + v.y * v.y) + (v.z * v.z + v.w * v.w);
#pragma unroll
    for (int d = 16; d; d >>= 1) q += __shfl_xor_sync(0xffffffffu, q, d);
    const float nrm = sqrtf(q);
    const float den = fmaxf(nrm, 1e-12f);
    const float inv = 1.0f / den;
    float4 o; o.x = v.x * inv; o.y = v.y * inv; o.z = v.z * inv; o.w = v.w * inv;
    ((float4*)(g_kn + (size_t)row * Hn))[lane] = o;
    if (lane == 0) g_meta[row] = make_float2(nrm, q * inv * inv);
}

// ---------------- sequential memory-matrix scan: 1 CTA per batch -------------
// 512 threads: thread = (row r=tid>>2, quarter q=tid&3), 32 cols (16 float2)
// of M per thread. 4 warps/SMSP fill the shuffle-chain/barrier latency.
// vp reduce = shfl d=1,2; energy coset = shfl d=4,8,16 (warp covers 8 rows).
// Quarters padded to 36-float offsets (144 B, 16-aligned; banks 0/4/8/12) ->
// aligned AND conflict-free LDS.128. cp.async ring: 8 slots, dist 4, wait 2.
#define SCAN_STEP(T, KC, KN) do {                                              \
    const int ns_ = ((T) + 1) & 7;                                             \
    float vp_ = acc + __shfl_xor_sync(0xffffffffu, acc, 1);                    \
    vp_ += __shfl_xor_sync(0xffffffffu, vp_, 2);                               \
    const float rr_ = fmaf(meta_cur.x, kv_cur, -vp_);                          \
    float e_ = rr_ * rr_;                                                      \
    e_ += __shfl_xor_sync(0xffffffffu, e_, 4);                                 \
    e_ += __shfl_xor_sync(0xffffffffu, e_, 8);                                 \
    e_ += __shfl_xor_sync(0xffffffffu, e_, 16);                                \
    _Pragma("unroll")                                                          \
    for (int j_ = 0; j_ < 8; ++j_) {                                           \
        float4 v_ = *(const float4*)(s_kn[ns_] + padoff + j_ * 4);             \
        KN[2 * j_]     = make_float2(v_.x, v_.y);                              \
        KN[2 * j_ + 1] = make_float2(v_.z, v_.w);                              \
    }                                                                          \
    const float  kv_nxt_   = s_kn[ns_][kvidx];                                 \
    const float2 meta_nxt_ = s_meta[ns_];                                      \
    if (lane == 0) s_part[(T) & 1][wid] = e_;                                  \
    if (tid < 32) {                                                            \
        if ((T) + 4 < Ln) {                                                    \
            const int pb_  = ((T) + 4) & 7;                                    \
            const int tok_ = s_seq[(T) + 4];                                   \
            cp_async16(&s_kn[pb_][(tid >> 3) * 36 + (tid & 7) * 4],            \
                       g_kn + (size_t)tok_ * Hn + tid * 4);                    \
            if (tid == 0) cp_async8(&s_meta[pb_], g_meta + tok_);              \
        }                                                                      \
        asm volatile("cp.async.commit_group;" ::: "memory");                   \
        asm volatile("cp.async.wait_group 2;" ::: "memory");                   \
    }                                                                          \
    __syncthreads();                                                           \
    float4 p0_ = ((const float4*)s_part[(T) & 1])[0];                          \
    float4 p1_ = ((const float4*)s_part[(T) & 1])[1];                          \
    float4 p2_ = ((const float4*)s_part[(T) & 1])[2];                          \
    float4 p3_ = ((const float4*)s_part[(T) & 1])[3];                          \
    float tot_ = (((p0_.x + p0_.y) + (p0_.z + p0_.w))                          \
               +  ((p1_.x + p1_.y) + (p1_.z + p1_.w)))                         \
               + (((p2_.x + p2_.y) + (p2_.z + p2_.w))                          \
               +  ((p3_.x + p3_.y) + (p3_.z + p3_.w)));                        \
    float2 a0_ = make_float2(0.f, 0.f), a1_ = a0_, a2_ = a0_, a3_ = a0_;       \
    if (tot_ * meta_cur.y * (1.0f / 16384.0f) >= 0.4f) {                       \
        const float2 rr2_ = make_float2(rr_, rr_);                             \
        _Pragma("unroll")                                                      \
        for (int j_ = 0; j_ < 16; j_ += 4) {                                   \
            M2[j_ + 0] = ffma2(rr2_, KC[j_ + 0], M2[j_ + 0]);                  \
            a0_ = ffma2(M2[j_ + 0], KN[j_ + 0], a0_);                          \
            M2[j_ + 1] = ffma2(rr2_, KC[j_ + 1], M2[j_ + 1]);                  \
            a1_ = ffma2(M2[j_ + 1], KN[j_ + 1], a1_);                          \
            M2[j_ + 2] = ffma2(rr2_, KC[j_ + 2], M2[j_ + 2]);                  \
            a2_ = ffma2(M2[j_ + 2], KN[j_ + 2], a2_);                          \
            M2[j_ + 3] = ffma2(rr2_, KC[j_ + 3], M2[j_ + 3]);                  \
            a3_ = ffma2(M2[j_ + 3], KN[j_ + 3], a3_);                          \
        }                                                                      \
    } else {                                                                   \
        _Pragma("unroll")                                                      \
        for (int j_ = 0; j_ < 16; j_ += 4) {                                   \
            a0_ = ffma2(M2[j_ + 0], KN[j_ + 0], a0_);                          \
            a1_ = ffma2(M2[j_ + 1], KN[j_ + 1], a1_);                          \
            a2_ = ffma2(M2[j_ + 2], KN[j_ + 2], a2_);                          \
            a3_ = ffma2(M2[j_ + 3], KN[j_ + 3], a3_);                          \
        }                                                                      \
    }                                                                          \
    acc = ((a0_.x + a0_.y) + (a1_.x + a1_.y))                                  \
        + ((a2_.x + a2_.y) + (a3_.x + a3_.y));                                 \
    kv_cur = kv_nxt_; meta_cur = meta_nxt_;                                    \
} while (0)

__global__ void __launch_bounds__(512, 1) scan_kernel(const int* __restrict__ seq)
{
    __shared__ __align__(16) float  s_kn[8][144];   // quarter q at offset q*36
    __shared__ __align__(16) float2 s_meta[8];
    __shared__ int   s_seq[Ln];
    __shared__ __align__(16) float s_part[2][16];

    const int b    = blockIdx.x;
    const int tid  = threadIdx.x;
    const int r    = tid >> 2;           // row 0..127
    const int q    = tid & 3;            // column quarter
    const int padoff = q * 36;
    const int kvidx  = (r >> 5) * 36 + (r & 31);
    const int lane = tid & 31;
    const int wid  = tid >> 5;

    for (int i = tid; i < Ln; i += 512) s_seq[i] = seq[(size_t)b * Ln + i];

    float2 M2[16];
#pragma unroll
    for (int j = 0; j < 16; ++j) M2[j] = make_float2(0.f, 0.f);
    __syncthreads();

    // prologue: preload ring slots 0..3 (tokens 0..3), padded layout
    if (tid < 128) {
        int slot = tid >> 5, c = tid & 31;
        int tok = s_seq[slot];
        *(float4*)(s_kn[slot] + (c >> 3) * 36 + (c & 7) * 4) =
            ((const float4*)(g_kn + (size_t)tok * Hn))[c];
    }
    if (tid < 4) s_meta[tid] = g_meta[s_seq[tid]];
    __syncthreads();

    // kn_0 into ka; M=0 so acc starts at 0
    float2 ka[16], kb[16];
#pragma unroll
    for (int j = 0; j < 8; ++j) {
        float4 v = *(const float4*)(s_kn[0] + padoff + j * 4);
        ka[2 * j]     = make_float2(v.x, v.y);
        ka[2 * j + 1] = make_float2(v.z, v.w);
    }
    float  acc      = 0.f;
    float  kv_cur   = s_kn[0][kvidx];
    float2 meta_cur = s_meta[0];

    // Ln-1 = 2047 steps: 1023 pairs + 1 tail step
    for (int t = 0; t + 1 < Ln - 1; t += 2) {
        SCAN_STEP(t,     ka, kb);
        SCAN_STEP(t + 1, kb, ka);
    }
    SCAN_STEP(Ln - 2, ka, kb);   // t = 2046 (even): current=ka, next->kb

    // epilogue: acc = M_final . kn_{Ln-1}; read = (M q)_r with q = kn*norm
    {
        float vp = acc + __shfl_xor_sync(0xffffffffu, acc, 1);
        vp += __shfl_xor_sync(0xffffffffu, vp, 2);
        if (q == 0) g_read[b * Hn + r] = vp * meta_cur.x;
    }
}

// ---------------- tmp = read @ rp_w^T + rp_b ---------------------------------
__global__ void __launch_bounds__(128) readrp_kernel(
    const float* __restrict__ rp_w, const float* __restrict__ rp_b)
{
    __shared__ float s_r[128];
    const int b = blockIdx.x;
    s_r[threadIdx.x] = g_read[b * Hn + threadIdx.x];
    __syncthreads();
    const int n = threadIdx.x;
    const float* wrow = rp_w + (size_t)n * Hn;
    float a0 = 0.f, a1 = 0.f, a2 = 0.f, a3 = 0.f;
#pragma unroll 8
    for (int j = 0; j < 128; j += 4) {
        a0 = fmaf(s_r[j + 0], wrow[j + 0], a0);
        a1 = fmaf(s_r[j + 1], wrow[j + 1], a1);
        a2 = fmaf(s_r[j + 2], wrow[j + 2], a2);
        a3 = fmaf(s_r[j + 3], wrow[j + 3], a3);
    }
    g_tmp[b * Hn + n] = (a0 + a1) + (a2 + a3) + rp_b[n];
}

// ---------------- logits: out[b][v] = tmp[b][:] . out_w[v][:] + out_b[v] -----
__global__ void __launch_bounds__(256) logits_kernel(
    const float* __restrict__ out_w, const float* __restrict__ out_b,
    float* __restrict__ outp)
{
    __shared__ __align__(16) float s_t[128][64];  // [j][b]
    for (int i = threadIdx.x; i < Bn * Hn; i += 256) {
        int b = i >> 7, j = i & 127;
        s_t[j][b] = g_tmp[i];
    }
    __syncthreads();

    const int v = blockIdx.x * 256 + threadIdx.x;
    const float4* wr = (const float4*)(out_w + (size_t)v * Hn);
    const float ob = out_b[v];
    float4 acc[16];
#pragma unroll
    for (int q = 0; q < 16; ++q) acc[q] = make_float4(ob, ob, ob, ob);

    for (int j4 = 0; j4 < 32; ++j4) {
        float4 w = wr[j4];
        float wj[4] = {w.x, w.y, w.z, w.w};
#pragma unroll
        for (int c = 0; c < 4; ++c) {
            const float4* tp = (const float4*)s_t[j4 * 4 + c];
#pragma unroll
            for (int q = 0; q < 16; ++q) {
                float4 t = tp[q];
                acc[q].x = fmaf(wj[c], t.x, acc[q].x);
                acc[q].y = fmaf(wj[c], t.y, acc[q].y);
                acc[q].z = fmaf(wj[c], t.z, acc[q].z);
                acc[q].w = fmaf(wj[c], t.w, acc[q].w);
            }
        }
    }
#pragma unroll
    for (int q = 0; q < 16; ++q) {
        outp[(size_t)(q * 4 + 0) * Vn + v] = acc[q].x;
        outp[(size_t)(q * 4 + 1) * Vn + v] = acc[q].y;
        outp[(size_t)(q * 4 + 2) * Vn + v] = acc[q].z;
        outp[(size_t)(q * 4 + 3) * Vn + v] = acc[q].w;
    }
}

// ---------------- launch ------------------------------------------------------
extern "C" void kernel_launch(void* const* d_in, const int* in_sizes, int n_in,
                              void* d_out, int out_size)
{
    const int*   seq    = (const int*)  d_in[0];
    const float* embedW = (const float*)d_in[1];
    const float* ff_w1  = (const float*)d_in[2];
    const float* ff_b1  = (const float*)d_in[3];
    const float* ff_w2  = (const float*)d_in[4];
    const float* ff_b2  = (const float*)d_in[5];
    const float* ln_g   = (const float*)d_in[6];
    const float* ln_b   = (const float*)d_in[7];
    const float* kp_w   = (const float*)d_in[8];
    const float* rp_w   = (const float*)d_in[9];
    const float* rp_b   = (const float*)d_in[10];
    const float* out_w  = (const float*)d_in[11];
    const float* out_b  = (const float*)d_in[12];
    float* outp = (float*)d_out;

    float *p_ff1, *p_x, *p_hn, *p_kt, *p_zero;
    cudaGetSymbolAddress((void**)&p_ff1,  g_ff1);
    cudaGetSymbolAddress((void**)&p_x,    g_x);
    cudaGetSymbolAddress((void**)&p_hn,   g_hn);
    cudaGetSymbolAddress((void**)&p_kt,   g_kt);
    cudaGetSymbolAddress((void**)&p_zero, g_zero);

    // vocab-table pipeline (32000 rows instead of 131072 tokens)
    sgemm_tn<true,  false><<<dim3(Vn / 128, 2), 256>>>(embedW, ff_w1, ff_b1, nullptr, p_ff1, 256, 128);
    sgemm_tn<false, true ><<<dim3(Vn / 128, 1), 256>>>(p_ff1,  ff_w2, ff_b2, embedW,  p_x,   128, 256);
    ln_kernel  <<<Vn / 8, 256>>>(ln_g, ln_b);
    sgemm_tn<false, false><<<dim3(Vn / 128, 1), 256>>>(p_hn,   kp_w,  p_zero, nullptr, p_kt,  128, 128);
    norm_kernel<<<Vn / 8, 256>>>();

    // sequential scan, one CTA per batch, 512 threads, M in registers
    scan_kernel<<<Bn, 512>>>(seq);

    // output head
    readrp_kernel<<<Bn, 128>>>(rp_w, rp_b);
    logits_kernel<<<Vn / 256, 256>>>(out_w, out_b, outp);
}

// round 11
// speedup vs baseline: 1.3835x; 1.3835x over previous
#include <cuda_runtime.h>
#include <math.h>
#include <stdint.h>

#define Bn 64
#define Ln 2048
#define Hn 128
#define Vn 32000

// ---------------- scratch (static device globals; no runtime allocation) ----
__device__ float  g_ff1[(size_t)Vn * 256];
__device__ float  g_x  [(size_t)Vn * Hn];
__device__ float  g_hn [(size_t)Vn * Hn];
__device__ float  g_kt [(size_t)Vn * Hn];
__device__ float  g_kn [(size_t)Vn * Hn];
__device__ float2 g_meta[Vn];            // (norm, ||kn||^2)
__device__ float  g_read[Bn * Hn];
__device__ float  g_tmp [Bn * Hn];
__device__ float  g_zero[256];           // zero-initialized: dummy bias

// packed fp32x2 FMA (Blackwell FFMA2 — only reachable via PTX fma.rn.f32x2)
__device__ __forceinline__ float2 ffma2(float2 a, float2 b, float2 c) {
    float2 d;
    asm("fma.rn.f32x2 %0, %1, %2, %3;"
        : "=l"(reinterpret_cast<unsigned long long&>(d))
        : "l"(reinterpret_cast<unsigned long long&>(a)),
          "l"(reinterpret_cast<unsigned long long&>(b)),
          "l"(reinterpret_cast<unsigned long long&>(c)));
    return d;
}

// async global->shared copies (no register landing; completion via groups)
__device__ __forceinline__ void cp_async16(void* sdst, const void* gsrc) {
    uint32_t sa = (uint32_t)__cvta_generic_to_shared(sdst);
    asm volatile("cp.async.cg.shared.global [%0], [%1], 16;" :: "r"(sa), "l"(gsrc));
}
__device__ __forceinline__ void cp_async8(void* sdst, const void* gsrc) {
    uint32_t sa = (uint32_t)__cvta_generic_to_shared(sdst);
    asm volatile("cp.async.ca.shared.global [%0], [%1], 8;" :: "r"(sa), "l"(gsrc));
}

// ---------------- generic fp32 GEMM, register double-buffered ----------------
// A: M x K row-major, B: N x K row-major. Tile 128x128, BK=32, 256 threads.
// Tile k+1 is LDG'd into registers DURING compute of tile k; STS after the
// barrier. Removes the exposed per-tile LDG latency (issue was 23.6%).
template <bool RELU, bool RESID>
__global__ void __launch_bounds__(256, 1) sgemm_tn(
    const float* __restrict__ A, const float* __restrict__ Bm,
    const float* __restrict__ bias, const float* __restrict__ resid,
    float* __restrict__ C, int Nn, int K)
{
    __shared__ float As[32][132];
    __shared__ float Bs[32][132];
    const int m0 = blockIdx.x * 128;
    const int n0 = blockIdx.y * 128;
    const int tid = threadIdx.x;
    const int tx = tid & 15;
    const int ty = tid >> 4;
    const int lrow = tid >> 3;       // 0..31
    const int lk   = (tid & 7) * 4;  // 0..28

    float2 acc2[8][4];
#pragma unroll
    for (int i = 0; i < 8; ++i)
#pragma unroll
        for (int j = 0; j < 4; ++j) acc2[i][j] = make_float2(0.f, 0.f);

    float4 av[4], bv[4];
#pragma unroll
    for (int p = 0; p < 4; ++p) {
        int row = lrow + p * 32;
        av[p] = *(const float4*)&A [(size_t)(m0 + row) * K + lk];
        bv[p] = *(const float4*)&Bm[(size_t)(n0 + row) * K + lk];
    }
#pragma unroll
    for (int p = 0; p < 4; ++p) {
        int row = lrow + p * 32;
        As[lk + 0][row] = av[p].x; As[lk + 1][row] = av[p].y;
        As[lk + 2][row] = av[p].z; As[lk + 3][row] = av[p].w;
        Bs[lk + 0][row] = bv[p].x; Bs[lk + 1][row] = bv[p].y;
        Bs[lk + 2][row] = bv[p].z; Bs[lk + 3][row] = bv[p].w;
    }
    __syncthreads();

    for (int k0 = 0; k0 < K; k0 += 32) {
        const bool more = (k0 + 32 < K);
        if (more) {
#pragma unroll
            for (int p = 0; p < 4; ++p) {
                int row = lrow + p * 32;
                av[p] = *(const float4*)&A [(size_t)(m0 + row) * K + k0 + 32 + lk];
                bv[p] = *(const float4*)&Bm[(size_t)(n0 + row) * K + k0 + 32 + lk];
            }
        }
#pragma unroll 8
        for (int kk = 0; kk < 32; ++kk) {
            float4 a0 = *(const float4*)&As[kk][ty * 8];
            float4 a1 = *(const float4*)&As[kk][ty * 8 + 4];
            float4 b0 = *(const float4*)&Bs[kk][tx * 8];
            float4 b1 = *(const float4*)&Bs[kk][tx * 8 + 4];
            float a[8] = {a0.x, a0.y, a0.z, a0.w, a1.x, a1.y, a1.z, a1.w};
            float2 bb[4] = {make_float2(b0.x, b0.y), make_float2(b0.z, b0.w),
                            make_float2(b1.x, b1.y), make_float2(b1.z, b1.w)};
#pragma unroll
            for (int i = 0; i < 8; ++i) {
                float2 ai = make_float2(a[i], a[i]);
#pragma unroll
                for (int j = 0; j < 4; ++j)
                    acc2[i][j] = ffma2(ai, bb[j], acc2[i][j]);
            }
        }
        __syncthreads();
        if (more) {
#pragma unroll
            for (int p = 0; p < 4; ++p) {
                int row = lrow + p * 32;
                As[lk + 0][row] = av[p].x; As[lk + 1][row] = av[p].y;
                As[lk + 2][row] = av[p].z; As[lk + 3][row] = av[p].w;
                Bs[lk + 0][row] = bv[p].x; Bs[lk + 1][row] = bv[p].y;
                Bs[lk + 2][row] = bv[p].z; Bs[lk + 3][row] = bv[p].w;
            }
            __syncthreads();
        }
    }

#pragma unroll
    for (int i = 0; i < 8; ++i) {
        const int m = m0 + ty * 8 + i;
#pragma unroll
        for (int j = 0; j < 4; ++j) {
            const int n = n0 + tx * 8 + j * 2;
            float vx = acc2[i][j].x + bias[n];
            float vy = acc2[i][j].y + bias[n + 1];
            if (RELU) { vx = fmaxf(vx, 0.f); vy = fmaxf(vy, 0.f); }
            if (RESID) {
                vx += resid[(size_t)m * Nn + n];
                vy += resid[(size_t)m * Nn + n + 1];
            }
            C[(size_t)m * Nn + n]     = vx;
            C[(size_t)m * Nn + n + 1] = vy;
        }
    }
}

// ---------------- LayerNorm: one warp per row of 128 -------------------------
__global__ void __launch_bounds__(256) ln_kernel(
    const float* __restrict__ g, const float* __restrict__ bparm)
{
    const int lane = threadIdx.x & 31;
    const int row  = blockIdx.x * 8 + (threadIdx.x >> 5);
    float4 v = ((const float4*)(g_x + (size_t)row * Hn))[lane];
    float s = (v.x + v.y) + (v.z + v.w);
#pragma unroll
    for (int d = 16; d; d >>= 1) s += __shfl_xor_sync(0xffffffffu, s, d);
    const float mu = s * (1.0f / 128.0f);
    float dx = v.x - mu, dy = v.y - mu, dz = v.z - mu, dw = v.w - mu;
    float q = (dx * dx + dy * dy) + (dz * dz + dw * dw);
#pragma unroll
    for (int d = 16; d; d >>= 1) q += __shfl_xor_sync(0xffffffffu, q, d);
    const float rstd = rsqrtf(q * (1.0f / 128.0f) + 1e-5f);
    float4 gg = ((const float4*)g)[lane];
    float4 bb = ((const float4*)bparm)[lane];
    float4 o;
    o.x = fmaf(dx * rstd, gg.x, bb.x);
    o.y = fmaf(dy * rstd, gg.y, bb.y);
    o.z = fmaf(dz * rstd, gg.z, bb.z);
    o.w = fmaf(dw * rstd, gg.w, bb.w);
    ((float4*)(g_hn + (size_t)row * Hn))[lane] = o;
}

// ---------------- row normalize k-table: kn + packed meta --------------------
__global__ void __launch_bounds__(256) norm_kernel()
{
    const int lane = threadIdx.x & 31;
    const int row  = blockIdx.x * 8 + (threadIdx.x >> 5);
    float4 v = ((const float4*)(g_kt + (size_t)row * Hn))[lane];
    float q = (v.x * v.x + v.y * v.y) + (v.z * v.z + v.w * v.w);
#pragma unroll
    for (int d = 16; d; d >>= 1) q += __shfl_xor_sync(0xffffffffu, q, d);
    const float nrm = sqrtf(q);
    const float den = fmaxf(nrm, 1e-12f);
    const float inv = 1.0f / den;
    float4 o; o.x = v.x * inv; o.y = v.y * inv; o.z = v.z * inv; o.w = v.w * inv;
    ((float4*)(g_kn + (size_t)row * Hn))[lane] = o;
    if (lane == 0) g_meta[row] = make_float2(nrm, q * inv * inv);
}

// ---------------- sequential memory-matrix scan: 1 CTA per batch -------------
// EXACTLY the R7 winner: 256 threads, thread=(row r=tid>>1, half hh=tid&1),
// 64 cols (32 float2) of M per thread, fused gated update+matvec post-barrier,
// kn_{t+1} preloaded into the second reg buffer pre-barrier, 4-chained-shfl
// energy coset reduce (d=2..16), cp.async 8-slot ring (dist 4, wait 2),
// halves padded to 68-float offsets (272 B, 16-aligned, conflict-free).
#define SCAN_STEP(T, KC, KN) do {                                              \
    const int ns_ = ((T) + 1) & 7;                                             \
    float vp_ = acc + __shfl_xor_sync(0xffffffffu, acc, 1);                    \
    const float rr_ = fmaf(meta_cur.x, kv_cur, -vp_);                          \
    float e_ = rr_ * rr_;                                                      \
    e_ += __shfl_xor_sync(0xffffffffu, e_, 2);                                 \
    e_ += __shfl_xor_sync(0xffffffffu, e_, 4);                                 \
    e_ += __shfl_xor_sync(0xffffffffu, e_, 8);                                 \
    e_ += __shfl_xor_sync(0xffffffffu, e_, 16);                                \
    _Pragma("unroll")                                                          \
    for (int j_ = 0; j_ < 16; ++j_) {                                          \
        float4 v_ = *(const float4*)(s_kn[ns_] + padoff + j_ * 4);             \
        KN[2 * j_]     = make_float2(v_.x, v_.y);                              \
        KN[2 * j_ + 1] = make_float2(v_.z, v_.w);                              \
    }                                                                          \
    const float  kv_nxt_   = s_kn[ns_][kvidx];                                 \
    const float2 meta_nxt_ = s_meta[ns_];                                      \
    if (lane == 0) s_part[(T) & 1][wid] = e_;                                  \
    if (tid < 32) {                                                            \
        if ((T) + 4 < Ln) {                                                    \
            const int pb_  = ((T) + 4) & 7;                                    \
            const int tok_ = s_seq[(T) + 4];                                   \
            cp_async16(&s_kn[pb_][(tid >> 4) * 68 + (tid & 15) * 4],           \
                       g_kn + (size_t)tok_ * Hn + tid * 4);                    \
            if (tid == 0) cp_async8(&s_meta[pb_], g_meta + tok_);              \
        }                                                                      \
        asm volatile("cp.async.commit_group;" ::: "memory");                   \
        asm volatile("cp.async.wait_group 2;" ::: "memory");                   \
    }                                                                          \
    __syncthreads();                                                           \
    float4 p0_ = ((const float4*)s_part[(T) & 1])[0];                          \
    float4 p1_ = ((const float4*)s_part[(T) & 1])[1];                          \
    float tot_ = ((p0_.x + p0_.y) + (p0_.z + p0_.w))                           \
               + ((p1_.x + p1_.y) + (p1_.z + p1_.w));                          \
    float2 a0_ = make_float2(0.f, 0.f), a1_ = a0_, a2_ = a0_, a3_ = a0_;       \
    if (tot_ * meta_cur.y * (1.0f / 16384.0f) >= 0.4f) {                       \
        const float2 rr2_ = make_float2(rr_, rr_);                             \
        _Pragma("unroll")                                                      \
        for (int j_ = 0; j_ < 32; j_ += 4) {                                   \
            M2[j_ + 0] = ffma2(rr2_, KC[j_ + 0], M2[j_ + 0]);                  \
            a0_ = ffma2(M2[j_ + 0], KN[j_ + 0], a0_);                          \
            M2[j_ + 1] = ffma2(rr2_, KC[j_ + 1], M2[j_ + 1]);                  \
            a1_ = ffma2(M2[j_ + 1], KN[j_ + 1], a1_);                          \
            M2[j_ + 2] = ffma2(rr2_, KC[j_ + 2], M2[j_ + 2]);                  \
            a2_ = ffma2(M2[j_ + 2], KN[j_ + 2], a2_);                          \
            M2[j_ + 3] = ffma2(rr2_, KC[j_ + 3], M2[j_ + 3]);                  \
            a3_ = ffma2(M2[j_ + 3], KN[j_ + 3], a3_);                          \
        }                                                                      \
    } else {                                                                   \
        _Pragma("unroll")                                                      \
        for (int j_ = 0; j_ < 32; j_ += 4) {                                   \
            a0_ = ffma2(M2[j_ + 0], KN[j_ + 0], a0_);                          \
            a1_ = ffma2(M2[j_ + 1], KN[j_ + 1], a1_);                          \
            a2_ = ffma2(M2[j_ + 2], KN[j_ + 2], a2_);                          \
            a3_ = ffma2(M2[j_ + 3], KN[j_ + 3], a3_);                          \
        }                                                                      \
    }                                                                          \
    acc = ((a0_.x + a0_.y) + (a1_.x + a1_.y))                                  \
        + ((a2_.x + a2_.y) + (a3_.x + a3_.y));                                 \
    kv_cur = kv_nxt_; meta_cur = meta_nxt_;                                    \
} while (0)

__global__ void __launch_bounds__(256, 1) scan_kernel(const int* __restrict__ seq)
{
    __shared__ __align__(16) float  s_kn[8][136];   // half offset 68 (272B, 16-aligned)
    __shared__ __align__(16) float2 s_meta[8];
    __shared__ int   s_seq[Ln];
    __shared__ __align__(16) float s_part[2][8];

    const int b    = blockIdx.x;
    const int tid  = threadIdx.x;
    const int r    = tid >> 1;
    const int hh   = tid & 1;
    const int padoff = hh * 68;
    const int kvidx  = (r >> 6) * 68 + (r & 63);
    const int lane = tid & 31;
    const int wid  = tid >> 5;

    for (int i = tid; i < Ln; i += 256) s_seq[i] = seq[(size_t)b * Ln + i];

    float2 M2[32];
#pragma unroll
    for (int j = 0; j < 32; ++j) M2[j] = make_float2(0.f, 0.f);
    __syncthreads();

    // prologue: preload ring slots 0..3 (tokens 0..3), padded layout
    if (tid < 128) {
        int slot = tid >> 5, c = tid & 31;
        int tok = s_seq[slot];
        *(float4*)(s_kn[slot] + (c >> 4) * 68 + (c & 15) * 4) =
            ((const float4*)(g_kn + (size_t)tok * Hn))[c];
    }
    if (tid < 4) s_meta[tid] = g_meta[s_seq[tid]];
    __syncthreads();

    // kn_0 into ka; M=0 so acc starts at 0
    float2 ka[32], kb[32];
#pragma unroll
    for (int j = 0; j < 16; ++j) {
        float4 v = *(const float4*)(s_kn[0] + padoff + j * 4);
        ka[2 * j]     = make_float2(v.x, v.y);
        ka[2 * j + 1] = make_float2(v.z, v.w);
    }
    float  acc      = 0.f;
    float  kv_cur   = s_kn[0][kvidx];
    float2 meta_cur = s_meta[0];

    // Ln-1 = 2047 steps: 1023 pairs + 1 tail step
    for (int t = 0; t + 1 < Ln - 1; t += 2) {
        SCAN_STEP(t,     ka, kb);
        SCAN_STEP(t + 1, kb, ka);
    }
    SCAN_STEP(Ln - 2, ka, kb);   // t = 2046 (even): current=ka, next->kb

    // epilogue: acc = M_final . kn_{Ln-1}; read = (M q)_r with q = kn*norm
    {
        float vp = acc + __shfl_xor_sync(0xffffffffu, acc, 1);
        if (hh == 0) g_read[b * Hn + r] = vp * meta_cur.x;
    }
}

// ---------------- tmp = read @ rp_w^T + rp_b ---------------------------------
__global__ void __launch_bounds__(128) readrp_kernel(
    const float* __restrict__ rp_w, const float* __restrict__ rp_b)
{
    __shared__ float s_r[128];
    const int b = blockIdx.x;
    s_r[threadIdx.x] = g_read[b * Hn + threadIdx.x];
    __syncthreads();
    const int n = threadIdx.x;
    const float* wrow = rp_w + (size_t)n * Hn;
    float a0 = 0.f, a1 = 0.f, a2 = 0.f, a3 = 0.f;
#pragma unroll 8
    for (int j = 0; j < 128; j += 4) {
        a0 = fmaf(s_r[j + 0], wrow[j + 0], a0);
        a1 = fmaf(s_r[j + 1], wrow[j + 1], a1);
        a2 = fmaf(s_r[j + 2], wrow[j + 2], a2);
        a3 = fmaf(s_r[j + 3], wrow[j + 3], a3);
    }
    g_tmp[b * Hn + n] = (a0 + a1) + (a2 + a3) + rp_b[n];
}

// ---------------- logits: out[b][v] = tmp[b][:] . out_w[v][:] + out_b[v] -----
__global__ void __launch_bounds__(256) logits_kernel(
    const float* __restrict__ out_w, const float* __restrict__ out_b,
    float* __restrict__ outp)
{
    __shared__ __align__(16) float s_t[128][64];  // [j][b]
    for (int i = threadIdx.x; i < Bn * Hn; i += 256) {
        int b = i >> 7, j = i & 127;
        s_t[j][b] = g_tmp[i];
    }
    __syncthreads();

    const int v = blockIdx.x * 256 + threadIdx.x;
    const float4* wr = (const float4*)(out_w + (size_t)v * Hn);
    const float ob = out_b[v];
    float4 acc[16];
#pragma unroll
    for (int q = 0; q < 16; ++q) acc[q] = make_float4(ob, ob, ob, ob);

    for (int j4 = 0; j4 < 32; ++j4) {
        float4 w = wr[j4];
        float wj[4] = {w.x, w.y, w.z, w.w};
#pragma unroll
        for (int c = 0; c < 4; ++c) {
            const float4* tp = (const float4*)s_t[j4 * 4 + c];
#pragma unroll
            for (int q = 0; q < 16; ++q) {
                float4 t = tp[q];
                acc[q].x = fmaf(wj[c], t.x, acc[q].x);
                acc[q].y = fmaf(wj[c], t.y, acc[q].y);
                acc[q].z = fmaf(wj[c], t.z, acc[q].z);
                acc[q].w = fmaf(wj[c], t.w, acc[q].w);
            }
        }
    }
#pragma unroll
    for (int q = 0; q < 16; ++q) {
        outp[(size_t)(q * 4 + 0) * Vn + v] = acc[q].x;
        outp[(size_t)(q * 4 + 1) * Vn + v] = acc[q].y;
        outp[(size_t)(q * 4 + 2) * Vn + v] = acc[q].z;
        outp[(size_t)(q * 4 + 3) * Vn + v] = acc[q].w;
    }
}

// ---------------- launch ------------------------------------------------------
extern "C" void kernel_launch(void* const* d_in, const int* in_sizes, int n_in,
                              void* d_out, int out_size)
{
    const int*   seq    = (const int*)  d_in[0];
    const float* embedW = (const float*)d_in[1];
    const float* ff_w1  = (const float*)d_in[2];
    const float* ff_b1  = (const float*)d_in[3];
    const float* ff_w2  = (const float*)d_in[4];
    const float* ff_b2  = (const float*)d_in[5];
    const float* ln_g   = (const float*)d_in[6];
    const float* ln_b   = (const float*)d_in[7];
    const float* kp_w   = (const float*)d_in[8];
    const float* rp_w   = (const float*)d_in[9];
    const float* rp_b   = (const float*)d_in[10];
    const float* out_w  = (const float*)d_in[11];
    const float* out_b  = (const float*)d_in[12];
    float* outp = (float*)d_out;

    float *p_ff1, *p_x, *p_hn, *p_kt, *p_zero;
    cudaGetSymbolAddress((void**)&p_ff1,  g_ff1);
    cudaGetSymbolAddress((void**)&p_x,    g_x);
    cudaGetSymbolAddress((void**)&p_hn,   g_hn);
    cudaGetSymbolAddress((void**)&p_kt,   g_kt);
    cudaGetSymbolAddress((void**)&p_zero, g_zero);

    // vocab-table pipeline (32000 rows instead of 131072 tokens)
    sgemm_tn<true,  false><<<dim3(Vn / 128, 2), 256>>>(embedW, ff_w1, ff_b1, nullptr, p_ff1, 256, 128);
    sgemm_tn<false, true ><<<dim3(Vn / 128, 1), 256>>>(p_ff1,  ff_w2, ff_b2, embedW,  p_x,   128, 256);
    ln_kernel  <<<Vn / 8, 256>>>(ln_g, ln_b);
    sgemm_tn<false, false><<<dim3(Vn / 128, 1), 256>>>(p_hn,   kp_w,  p_zero, nullptr, p_kt,  128, 128);
    norm_kernel<<<Vn / 8, 256>>>();

    // sequential scan, one CTA per batch, 256 threads, M in registers (R7)
    scan_kernel<<<Bn, 256>>>(seq);

    // output head
    readrp_kernel<<<Bn, 128>>>(rp_w, rp_b);
    logits_kernel<<<Vn / 256, 256>>>(out_w, out_b, outp);
}

// round 12
// speedup vs baseline: 1.3890x; 1.0040x over previous
#include <cuda_runtime.h>
#include <math.h>
#include <stdint.h>

#define Bn 64
#define Ln 2048
#define Hn 128
#define Vn 32000

// ---------------- scratch (static device globals; no runtime allocation) ----
__device__ float  g_ff1[(size_t)Vn * 256];
__device__ float  g_x  [(size_t)Vn * Hn];
__device__ float  g_hn [(size_t)Vn * Hn];
__device__ float  g_kt [(size_t)Vn * Hn];
__device__ float  g_kn [(size_t)Vn * Hn];
__device__ float2 g_meta[Vn];            // (norm, ||kn||^2)
__device__ float  g_read[Bn * Hn];
__device__ float  g_tmp [Bn * Hn];
__device__ float  g_zero[256];           // zero-initialized: dummy bias

// packed fp32x2 FMA (Blackwell FFMA2 — only reachable via PTX fma.rn.f32x2)
__device__ __forceinline__ float2 ffma2(float2 a, float2 b, float2 c) {
    float2 d;
    asm("fma.rn.f32x2 %0, %1, %2, %3;"
        : "=l"(reinterpret_cast<unsigned long long&>(d))
        : "l"(reinterpret_cast<unsigned long long&>(a)),
          "l"(reinterpret_cast<unsigned long long&>(b)),
          "l"(reinterpret_cast<unsigned long long&>(c)));
    return d;
}

// async global->shared copies (no register landing; completion via groups)
__device__ __forceinline__ void cp_async16(void* sdst, const void* gsrc) {
    uint32_t sa = (uint32_t)__cvta_generic_to_shared(sdst);
    asm volatile("cp.async.cg.shared.global [%0], [%1], 16;" :: "r"(sa), "l"(gsrc));
}
__device__ __forceinline__ void cp_async8(void* sdst, const void* gsrc) {
    uint32_t sa = (uint32_t)__cvta_generic_to_shared(sdst);
    asm volatile("cp.async.ca.shared.global [%0], [%1], 8;" :: "r"(sa), "l"(gsrc));
}

// ---------------- generic fp32 GEMM (R7 version — reverted) ------------------
template <bool RELU, bool RESID>
__global__ void __launch_bounds__(256, 2) sgemm_tn(
    const float* __restrict__ A, const float* __restrict__ Bm,
    const float* __restrict__ bias, const float* __restrict__ resid,
    float* __restrict__ C, int Nn, int K)
{
    __shared__ float As[32][132];
    __shared__ float Bs[32][132];
    const int m0 = blockIdx.x * 128;
    const int n0 = blockIdx.y * 128;
    const int tid = threadIdx.x;
    const int tx = tid & 15;
    const int ty = tid >> 4;
    const int lrow = tid >> 3;       // 0..31
    const int lk   = (tid & 7) * 4;  // 0..28

    float2 acc2[8][4];
#pragma unroll
    for (int i = 0; i < 8; ++i)
#pragma unroll
        for (int j = 0; j < 4; ++j) acc2[i][j] = make_float2(0.f, 0.f);

    for (int k0 = 0; k0 < K; k0 += 32) {
#pragma unroll
        for (int p = 0; p < 4; ++p) {
            int row = lrow + p * 32;
            float4 av = *(const float4*)&A [(size_t)(m0 + row) * K + k0 + lk];
            As[lk + 0][row] = av.x; As[lk + 1][row] = av.y;
            As[lk + 2][row] = av.z; As[lk + 3][row] = av.w;
            float4 bv = *(const float4*)&Bm[(size_t)(n0 + row) * K + k0 + lk];
            Bs[lk + 0][row] = bv.x; Bs[lk + 1][row] = bv.y;
            Bs[lk + 2][row] = bv.z; Bs[lk + 3][row] = bv.w;
        }
        __syncthreads();
#pragma unroll 8
        for (int kk = 0; kk < 32; ++kk) {
            float4 a0 = *(const float4*)&As[kk][ty * 8];
            float4 a1 = *(const float4*)&As[kk][ty * 8 + 4];
            float4 b0 = *(const float4*)&Bs[kk][tx * 8];
            float4 b1 = *(const float4*)&Bs[kk][tx * 8 + 4];
            float a[8] = {a0.x, a0.y, a0.z, a0.w, a1.x, a1.y, a1.z, a1.w};
            float2 bb[4] = {make_float2(b0.x, b0.y), make_float2(b0.z, b0.w),
                            make_float2(b1.x, b1.y), make_float2(b1.z, b1.w)};
#pragma unroll
            for (int i = 0; i < 8; ++i) {
                float2 ai = make_float2(a[i], a[i]);
#pragma unroll
                for (int j = 0; j < 4; ++j)
                    acc2[i][j] = ffma2(ai, bb[j], acc2[i][j]);
            }
        }
        __syncthreads();
    }

#pragma unroll
    for (int i = 0; i < 8; ++i) {
        const int m = m0 + ty * 8 + i;
#pragma unroll
        for (int j = 0; j < 4; ++j) {
            const int n = n0 + tx * 8 + j * 2;
            float vx = acc2[i][j].x + bias[n];
            float vy = acc2[i][j].y + bias[n + 1];
            if (RELU) { vx = fmaxf(vx, 0.f); vy = fmaxf(vy, 0.f); }
            if (RESID) {
                vx += resid[(size_t)m * Nn + n];
                vy += resid[(size_t)m * Nn + n + 1];
            }
            C[(size_t)m * Nn + n]     = vx;
            C[(size_t)m * Nn + n + 1] = vy;
        }
    }
}

// ---------------- LayerNorm: one warp per row of 128 -------------------------
__global__ void __launch_bounds__(256) ln_kernel(
    const float* __restrict__ g, const float* __restrict__ bparm)
{
    const int lane = threadIdx.x & 31;
    const int row  = blockIdx.x * 8 + (threadIdx.x >> 5);
    float4 v = ((const float4*)(g_x + (size_t)row * Hn))[lane];
    float s = (v.x + v.y) + (v.z + v.w);
#pragma unroll
    for (int d = 16; d; d >>= 1) s += __shfl_xor_sync(0xffffffffu, s, d);
    const float mu = s * (1.0f / 128.0f);
    float dx = v.x - mu, dy = v.y - mu, dz = v.z - mu, dw = v.w - mu;
    float q = (dx * dx + dy * dy) + (dz * dz + dw * dw);
#pragma unroll
    for (int d = 16; d; d >>= 1) q += __shfl_xor_sync(0xffffffffu, q, d);
    const float rstd = rsqrtf(q * (1.0f / 128.0f) + 1e-5f);
    float4 gg = ((const float4*)g)[lane];
    float4 bb = ((const float4*)bparm)[lane];
    float4 o;
    o.x = fmaf(dx * rstd, gg.x, bb.x);
    o.y = fmaf(dy * rstd, gg.y, bb.y);
    o.z = fmaf(dz * rstd, gg.z, bb.z);
    o.w = fmaf(dw * rstd, gg.w, bb.w);
    ((float4*)(g_hn + (size_t)row * Hn))[lane] = o;
}

// ---------------- row normalize k-table: kn + packed meta --------------------
__global__ void __launch_bounds__(256) norm_kernel()
{
    const int lane = threadIdx.x & 31;
    const int row  = blockIdx.x * 8 + (threadIdx.x >> 5);
    float4 v = ((const float4*)(g_kt + (size_t)row * Hn))[lane];
    float q = (v.x * v.x + v.y * v.y) + (v.z * v.z + v.w * v.w);
#pragma unroll
    for (int d = 16; d; d >>= 1) q += __shfl_xor_sync(0xffffffffu, q, d);
    const float nrm = sqrtf(q);
    const float den = fmaxf(nrm, 1e-12f);
    const float inv = 1.0f / den;
    float4 o; o.x = v.x * inv; o.y = v.y * inv; o.z = v.z * inv; o.w = v.w * inv;
    ((float4*)(g_kn + (size_t)row * Hn))[lane] = o;
    if (lane == 0) g_meta[row] = make_float2(nrm, q * inv * inv);
}

// ---------------- one-step-pipelined scan: 1 CTA per batch -------------------
// Algebra (proven in R4/R6): gate of step T-1 resolves at step T;
//   vp_T = M_{T-2}.kn_T + g_{T-1}*rr_{T-1}*(kn_{T-1}.kn_T)
// Schedule (R7 lessons): update reads kn_{T-1} from REGISTERS (buffer KP),
// the SAME buffer is then reloaded with kn_{T+1} (16 LDS.128, hidden under the
// update FFMAs) and used by the matvec -> only 2 alternating k buffers.
// e+pd shuffle chains issue BEFORE the ~290-cyc fused stream; STS after it.
#define SCAN_STEP(T, KP) do {                                                   \
    const int ns_ = ((T) + 1) & 7;                                              \
    /* gate + dot correction of step T-1 (partials in s_part[(T-1)&1]) */       \
    float4 q0_ = ((const float4*)s_part[((T) + 1) & 1])[0];                      \
    float4 q1_ = ((const float4*)s_part[((T) + 1) & 1])[1];                      \
    float4 q2_ = ((const float4*)s_part[((T) + 1) & 1])[2];                      \
    float4 q3_ = ((const float4*)s_part[((T) + 1) & 1])[3];                      \
    float te_ = ((q0_.x + q0_.z) + (q1_.x + q1_.z))                              \
              + ((q2_.x + q2_.z) + (q3_.x + q3_.z));                             \
    float dc_ = ((q0_.y + q0_.w) + (q1_.y + q1_.w))                              \
              + ((q2_.y + q2_.w) + (q3_.y + q3_.w));                             \
    const bool g_ = te_ * meta_prev.y * (1.0f / 16384.0f) >= 0.4f;               \
    float vp_ = vp_acc;                                                          \
    if (g_) vp_ = fmaf(rr_prev, dc_, vp_);                                       \
    const float rr_ = fmaf(meta_cur.x, kvc, -vp_);                               \
    const float  kvn_      = s_kn[ns_][kvidx];                                   \
    const float2 meta_nxt_ = s_meta[ns_];                                        \
    /* interleaved chains: e = ||rr||^2 partial, pd = kn_T.kn_{T+1} partial */   \
    float e_  = rr_ * rr_;                                                       \
    float pd_ = kvc * kvn_;                                                      \
    e_  += __shfl_xor_sync(0xffffffffu, e_,  2);                                 \
    pd_ += __shfl_xor_sync(0xffffffffu, pd_, 2);                                 \
    e_  += __shfl_xor_sync(0xffffffffu, e_,  4);                                 \
    pd_ += __shfl_xor_sync(0xffffffffu, pd_, 4);                                 \
    e_  += __shfl_xor_sync(0xffffffffu, e_,  8);                                 \
    pd_ += __shfl_xor_sync(0xffffffffu, pd_, 8);                                 \
    e_  += __shfl_xor_sync(0xffffffffu, e_,  16);                                \
    pd_ += __shfl_xor_sync(0xffffffffu, pd_, 16);                                \
    /* fused: gated update (KP = kn_{T-1}, regs) -> reload KP <- kn_{T+1} ->    \
       matvec acc = M_{T-1}.kn_{T+1} */                                          \
    if (g_) {                                                                    \
        const float2 rr2_ = make_float2(rr_prev, rr_prev);                       \
        _Pragma("unroll")                                                        \
        for (int j_ = 0; j_ < 32; ++j_) M2[j_] = ffma2(rr2_, KP[j_], M2[j_]);    \
    }                                                                            \
    _Pragma("unroll")                                                            \
    for (int j_ = 0; j_ < 16; ++j_) {                                            \
        float4 v_ = *(const float4*)(s_kn[ns_] + padoff + j_ * 4);               \
        KP[2 * j_]     = make_float2(v_.x, v_.y);                                \
        KP[2 * j_ + 1] = make_float2(v_.z, v_.w);                                \
    }                                                                            \
    float2 a0_ = make_float2(0.f, 0.f), a1_ = a0_, a2_ = a0_, a3_ = a0_;         \
    _Pragma("unroll")                                                            \
    for (int j_ = 0; j_ < 32; j_ += 4) {                                         \
        a0_ = ffma2(M2[j_ + 0], KP[j_ + 0], a0_);                                \
        a1_ = ffma2(M2[j_ + 1], KP[j_ + 1], a1_);                                \
        a2_ = ffma2(M2[j_ + 2], KP[j_ + 2], a2_);                                \
        a3_ = ffma2(M2[j_ + 3], KP[j_ + 3], a3_);                                \
    }                                                                            \
    float an_ = ((a0_.x + a0_.y) + (a1_.x + a1_.y))                              \
              + ((a2_.x + a2_.y) + (a3_.x + a3_.y));                             \
    an_ += __shfl_xor_sync(0xffffffffu, an_, 1);                                 \
    /* publish partials (chains resolved under the FFMA stream above) */         \
    if (lane == 0) ((float2*)s_part[(T) & 1])[wid] = make_float2(e_, pd_);       \
    if (tid < 32) {                                                              \
        if ((T) + 4 < Ln) {                                                      \
            const int pb_  = ((T) + 4) & 7;                                      \
            const int tok_ = s_seq[(T) + 4];                                     \
            cp_async16(&s_kn[pb_][(tid >> 4) * 68 + (tid & 15) * 4],             \
                       g_kn + (size_t)tok_ * Hn + tid * 4);                      \
            if (tid == 0) cp_async8(&s_meta[pb_], g_meta + tok_);                \
        }                                                                        \
        asm volatile("cp.async.commit_group;" ::: "memory");                     \
        asm volatile("cp.async.wait_group 2;" ::: "memory");                     \
    }                                                                            \
    __syncthreads();                                                             \
    rr_prev = rr_; kvc = kvn_;                                                   \
    meta_prev = meta_cur; meta_cur = meta_nxt_;                                  \
    vp_acc = an_;                                                                \
} while (0)

__global__ void __launch_bounds__(256, 1) scan_kernel(const int* __restrict__ seq)
{
    __shared__ __align__(16) float  s_kn[8][136];   // half offset 68 (272B, 16-aligned)
    __shared__ __align__(16) float2 s_meta[8];
    __shared__ int   s_seq[Ln];
    __shared__ __align__(16) float s_part[2][16];   // 8 warps x (e, pd)

    const int b    = blockIdx.x;
    const int tid  = threadIdx.x;
    const int r    = tid >> 1;
    const int hh   = tid & 1;
    const int padoff = hh * 68;
    const int kvidx  = (r >> 6) * 68 + (r & 63);
    const int lane = tid & 31;
    const int wid  = tid >> 5;

    for (int i = tid; i < Ln; i += 256) s_seq[i] = seq[(size_t)b * Ln + i];

    float2 M2[32];
#pragma unroll
    for (int j = 0; j < 32; ++j) M2[j] = make_float2(0.f, 0.f);
    __syncthreads();

    // prologue: sync-load ring slots 0..3, async slot 4
    if (tid < 128) {
        int slot = tid >> 5, c = tid & 31;
        int tok = s_seq[slot];
        *(float4*)(s_kn[slot] + (c >> 4) * 68 + (c & 15) * 4) =
            ((const float4*)(g_kn + (size_t)tok * Hn))[c];
    }
    if (tid < 4) s_meta[tid] = g_meta[s_seq[tid]];
    __syncthreads();
    if (tid < 32) {
        int tok = s_seq[4];
        cp_async16(&s_kn[4][(tid >> 4) * 68 + (tid & 15) * 4],
                   g_kn + (size_t)tok * Hn + tid * 4);
        if (tid == 0) cp_async8(&s_meta[4], g_meta + tok);
        asm volatile("cp.async.commit_group;" ::: "memory");
    }

    // ka <- kn_0, kb <- kn_1
    float2 ka[32], kb[32];
#pragma unroll
    for (int j = 0; j < 16; ++j) {
        float4 v0 = *(const float4*)(s_kn[0] + padoff + j * 4);
        float4 v1 = *(const float4*)(s_kn[1] + padoff + j * 4);
        ka[2 * j]     = make_float2(v0.x, v0.y);
        ka[2 * j + 1] = make_float2(v0.z, v0.w);
        kb[2 * j]     = make_float2(v1.x, v1.y);
        kb[2 * j + 1] = make_float2(v1.z, v1.w);
    }

    // step 0: M = 0 -> vp_0 = 0, rr_0 = norm_0 * kn_0[r]; publish (e_0, pd_0)
    float2 m0 = s_meta[0], m1 = s_meta[1];
    const float kvc0 = s_kn[0][kvidx];
    const float kv1  = s_kn[1][kvidx];
    float rr0 = m0.x * kvc0;
    {
        float e  = rr0 * rr0;
        float pd = kvc0 * kv1;
        e  += __shfl_xor_sync(0xffffffffu, e,  2);
        pd += __shfl_xor_sync(0xffffffffu, pd, 2);
        e  += __shfl_xor_sync(0xffffffffu, e,  4);
        pd += __shfl_xor_sync(0xffffffffu, pd, 4);
        e  += __shfl_xor_sync(0xffffffffu, e,  8);
        pd += __shfl_xor_sync(0xffffffffu, pd, 8);
        e  += __shfl_xor_sync(0xffffffffu, e,  16);
        pd += __shfl_xor_sync(0xffffffffu, pd, 16);
        if (lane == 0) ((float2*)s_part[0])[wid] = make_float2(e, pd);
    }
    __syncthreads();

    float  rr_prev = rr0, kvc = kv1, vp_acc = 0.f;
    float2 meta_prev = m0, meta_cur = m1;

    // steps 1..2046: 1023 pairs (odd step uses ka as KP, even uses kb)
    for (int t = 1; t <= Ln - 3; t += 2) {
        SCAN_STEP(t,     ka);
        SCAN_STEP(t + 1, kb);
    }

    // epilogue = step 2047 head: resolve gate 2046, corrected vp is the read
    {
        float4 q0 = ((const float4*)s_part[0])[0];
        float4 q1 = ((const float4*)s_part[0])[1];
        float4 q2 = ((const float4*)s_part[0])[2];
        float4 q3 = ((const float4*)s_part[0])[3];
        float te = ((q0.x + q0.z) + (q1.x + q1.z)) + ((q2.x + q2.z) + (q3.x + q3.z));
        float dc = ((q0.y + q0.w) + (q1.y + q1.w)) + ((q2.y + q2.w) + (q3.y + q3.w));
        float vp = vp_acc;
        if (te * meta_prev.y * (1.0f / 16384.0f) >= 0.4f)
            vp = fmaf(rr_prev, dc, vp);
        if (hh == 0) g_read[b * Hn + r] = vp * meta_cur.x;   // q = kn_{L-1}*norm
    }
}

// ---------------- tmp = read @ rp_w^T + rp_b ---------------------------------
__global__ void __launch_bounds__(128) readrp_kernel(
    const float* __restrict__ rp_w, const float* __restrict__ rp_b)
{
    __shared__ float s_r[128];
    const int b = blockIdx.x;
    s_r[threadIdx.x] = g_read[b * Hn + threadIdx.x];
    __syncthreads();
    const int n = threadIdx.x;
    const float* wrow = rp_w + (size_t)n * Hn;
    float a0 = 0.f, a1 = 0.f, a2 = 0.f, a3 = 0.f;
#pragma unroll 8
    for (int j = 0; j < 128; j += 4) {
        a0 = fmaf(s_r[j + 0], wrow[j + 0], a0);
        a1 = fmaf(s_r[j + 1], wrow[j + 1], a1);
        a2 = fmaf(s_r[j + 2], wrow[j + 2], a2);
        a3 = fmaf(s_r[j + 3], wrow[j + 3], a3);
    }
    g_tmp[b * Hn + n] = (a0 + a1) + (a2 + a3) + rp_b[n];
}

// ---------------- logits: out[b][v] = tmp[b][:] . out_w[v][:] + out_b[v] -----
__global__ void __launch_bounds__(256) logits_kernel(
    const float* __restrict__ out_w, const float* __restrict__ out_b,
    float* __restrict__ outp)
{
    __shared__ __align__(16) float s_t[128][64];  // [j][b]
    for (int i = threadIdx.x; i < Bn * Hn; i += 256) {
        int b = i >> 7, j = i & 127;
        s_t[j][b] = g_tmp[i];
    }
    __syncthreads();

    const int v = blockIdx.x * 256 + threadIdx.x;
    const float4* wr = (const float4*)(out_w + (size_t)v * Hn);
    const float ob = out_b[v];
    float4 acc[16];
#pragma unroll
    for (int q = 0; q < 16; ++q) acc[q] = make_float4(ob, ob, ob, ob);

    for (int j4 = 0; j4 < 32; ++j4) {
        float4 w = wr[j4];
        float wj[4] = {w.x, w.y, w.z, w.w};
#pragma unroll
        for (int c = 0; c < 4; ++c) {
            const float4* tp = (const float4*)s_t[j4 * 4 + c];
#pragma unroll
            for (int q = 0; q < 16; ++q) {
                float4 t = tp[q];
                acc[q].x = fmaf(wj[c], t.x, acc[q].x);
                acc[q].y = fmaf(wj[c], t.y, acc[q].y);
                acc[q].z = fmaf(wj[c], t.z, acc[q].z);
                acc[q].w = fmaf(wj[c], t.w, acc[q].w);
            }
        }
    }
#pragma unroll
    for (int q = 0; q < 16; ++q) {
        outp[(size_t)(q * 4 + 0) * Vn + v] = acc[q].x;
        outp[(size_t)(q * 4 + 1) * Vn + v] = acc[q].y;
        outp[(size_t)(q * 4 + 2) * Vn + v] = acc[q].z;
        outp[(size_t)(q * 4 + 3) * Vn + v] = acc[q].w;
    }
}

// ---------------- launch ------------------------------------------------------
extern "C" void kernel_launch(void* const* d_in, const int* in_sizes, int n_in,
                              void* d_out, int out_size)
{
    const int*   seq    = (const int*)  d_in[0];
    const float* embedW = (const float*)d_in[1];
    const float* ff_w1  = (const float*)d_in[2];
    const float* ff_b1  = (const float*)d_in[3];
    const float* ff_w2  = (const float*)d_in[4];
    const float* ff_b2  = (const float*)d_in[5];
    const float* ln_g   = (const float*)d_in[6];
    const float* ln_b   = (const float*)d_in[7];
    const float* kp_w   = (const float*)d_in[8];
    const float* rp_w   = (const float*)d_in[9];
    const float* rp_b   = (const float*)d_in[10];
    const float* out_w  = (const float*)d_in[11];
    const float* out_b  = (const float*)d_in[12];
    float* outp = (float*)d_out;

    float *p_ff1, *p_x, *p_hn, *p_kt, *p_zero;
    cudaGetSymbolAddress((void**)&p_ff1,  g_ff1);
    cudaGetSymbolAddress((void**)&p_x,    g_x);
    cudaGetSymbolAddress((void**)&p_hn,   g_hn);
    cudaGetSymbolAddress((void**)&p_kt,   g_kt);
    cudaGetSymbolAddress((void**)&p_zero, g_zero);

    // vocab-table pipeline (32000 rows instead of 131072 tokens)
    sgemm_tn<true,  false><<<dim3(Vn / 128, 2), 256>>>(embedW, ff_w1, ff_b1, nullptr, p_ff1, 256, 128);
    sgemm_tn<false, true ><<<dim3(Vn / 128, 1), 256>>>(p_ff1,  ff_w2, ff_b2, embedW,  p_x,   128, 256);
    ln_kernel  <<<Vn / 8, 256>>>(ln_g, ln_b);
    sgemm_tn<false, false><<<dim3(Vn / 128, 1), 256>>>(p_hn,   kp_w,  p_zero, nullptr, p_kt,  128, 128);
    norm_kernel<<<Vn / 8, 256>>>();

    // one-step-pipelined sequential scan, one CTA per batch, M in registers
    scan_kernel<<<Bn, 256>>>(seq);

    // output head
    readrp_kernel<<<Bn, 128>>>(rp_w, rp_b);
    logits_kernel<<<Vn / 256, 256>>>(out_w, out_b, outp);
}

// round 15
// speedup vs baseline: 1.4871x; 1.0706x over previous
#include <cuda_runtime.h>
#include <math.h>
#include <stdint.h>

#define Bn 64
#define Ln 2048
#define Hn 128
#define Vn 32000

// ---------------- scratch (static device globals; no runtime allocation) ----
__device__ float  g_ff1[(size_t)Vn * 256];
__device__ float  g_x  [(size_t)Vn * Hn];
__device__ float  g_hn [(size_t)Vn * Hn];
__device__ float  g_kt [(size_t)Vn * Hn];
__device__ float  g_kn [(size_t)Vn * Hn];
__device__ float2 g_meta[Vn];            // (norm, ||kn||^2)
__device__ float  g_read[Bn * Hn];
__device__ float  g_tmp [Bn * Hn];
__device__ float  g_zero[256];           // zero-initialized: dummy bias

// packed fp32x2 FMA (Blackwell FFMA2 — only reachable via PTX fma.rn.f32x2)
__device__ __forceinline__ float2 ffma2(float2 a, float2 b, float2 c) {
    float2 d;
    asm("fma.rn.f32x2 %0, %1, %2, %3;"
        : "=l"(reinterpret_cast<unsigned long long&>(d))
        : "l"(reinterpret_cast<unsigned long long&>(a)),
          "l"(reinterpret_cast<unsigned long long&>(b)),
          "l"(reinterpret_cast<unsigned long long&>(c)));
    return d;
}

// async global->shared copies (no register landing; completion via groups)
__device__ __forceinline__ void cp_async16(void* sdst, const void* gsrc) {
    uint32_t sa = (uint32_t)__cvta_generic_to_shared(sdst);
    asm volatile("cp.async.cg.shared.global [%0], [%1], 16;" :: "r"(sa), "l"(gsrc));
}
__device__ __forceinline__ void cp_async8(void* sdst, const void* gsrc) {
    uint32_t sa = (uint32_t)__cvta_generic_to_shared(sdst);
    asm volatile("cp.async.ca.shared.global [%0], [%1], 8;" :: "r"(sa), "l"(gsrc));
}

// ---------------- generic fp32 GEMM, conflict-free B reads --------------------
// A: M x K row-major, B: N x K row-major. Tile 128x128, BK=32, 256 threads,
// 8x8 per thread. Thread (tx,ty) owns rows ty*8..ty*8+7 and the STRIDED
// columns {tx + 16*j}. B inner-loop reads are scalar LDS at 16 consecutive
// banks (ty-pair broadcast) -> NO bank conflicts (old tx*8 float4 pattern was
// 4-way conflicted, saturating L1 at ~50%).
template <bool RELU, bool RESID>
__global__ void __launch_bounds__(256, 2) sgemm_tn(
    const float* __restrict__ A, const float* __restrict__ Bm,
    const float* __restrict__ bias, const float* __restrict__ resid,
    float* __restrict__ C, int Nn, int K)
{
    __shared__ float As[32][132];
    __shared__ float Bs[32][132];
    const int m0 = blockIdx.x * 128;
    const int n0 = blockIdx.y * 128;
    const int tid = threadIdx.x;
    const int tx = tid & 15;
    const int ty = tid >> 4;
    const int lrow = tid >> 3;       // 0..31
    const int lk   = (tid & 7) * 4;  // 0..28

    float2 acc2[8][4];
#pragma unroll
    for (int i = 0; i < 8; ++i)
#pragma unroll
        for (int j = 0; j < 4; ++j) acc2[i][j] = make_float2(0.f, 0.f);

    for (int k0 = 0; k0 < K; k0 += 32) {
#pragma unroll
        for (int p = 0; p < 4; ++p) {
            int row = lrow + p * 32;
            float4 av = *(const float4*)&A [(size_t)(m0 + row) * K + k0 + lk];
            As[lk + 0][row] = av.x; As[lk + 1][row] = av.y;
            As[lk + 2][row] = av.z; As[lk + 3][row] = av.w;
            float4 bv = *(const float4*)&Bm[(size_t)(n0 + row) * K + k0 + lk];
            Bs[lk + 0][row] = bv.x; Bs[lk + 1][row] = bv.y;
            Bs[lk + 2][row] = bv.z; Bs[lk + 3][row] = bv.w;
        }
        __syncthreads();
#pragma unroll 8
        for (int kk = 0; kk < 32; ++kk) {
            float4 a0 = *(const float4*)&As[kk][ty * 8];
            float4 a1 = *(const float4*)&As[kk][ty * 8 + 4];
            float a[8] = {a0.x, a0.y, a0.z, a0.w, a1.x, a1.y, a1.z, a1.w};
            // strided, conflict-free scalar B reads: columns tx + 16*j
            float b[8];
#pragma unroll
            for (int j = 0; j < 8; ++j) b[j] = Bs[kk][tx + 16 * j];
            float2 bb[4] = {make_float2(b[0], b[1]), make_float2(b[2], b[3]),
                            make_float2(b[4], b[5]), make_float2(b[6], b[7])};
#pragma unroll
            for (int i = 0; i < 8; ++i) {
                float2 ai = make_float2(a[i], a[i]);
#pragma unroll
                for (int j = 0; j < 4; ++j)
                    acc2[i][j] = ffma2(ai, bb[j], acc2[i][j]);
            }
        }
        __syncthreads();
    }

#pragma unroll
    for (int i = 0; i < 8; ++i) {
        const int m = m0 + ty * 8 + i;
#pragma unroll
        for (int j = 0; j < 4; ++j) {
            const int nx = n0 + tx + 32 * j;        // column of acc2[i][j].x
            const int ny = nx + 16;                 // column of acc2[i][j].y
            float vx = acc2[i][j].x + bias[nx];
            float vy = acc2[i][j].y + bias[ny];
            if (RELU) { vx = fmaxf(vx, 0.f); vy = fmaxf(vy, 0.f); }
            if (RESID) {
                vx += resid[(size_t)m * Nn + nx];
                vy += resid[(size_t)m * Nn + ny];
            }
            C[(size_t)m * Nn + nx] = vx;
            C[(size_t)m * Nn + ny] = vy;
        }
    }
}

// ---------------- LayerNorm: one warp per row of 128 -------------------------
__global__ void __launch_bounds__(256) ln_kernel(
    const float* __restrict__ g, const float* __restrict__ bparm)
{
    const int lane = threadIdx.x & 31;
    const int row  = blockIdx.x * 8 + (threadIdx.x >> 5);
    float4 v = ((const float4*)(g_x + (size_t)row * Hn))[lane];
    float s = (v.x + v.y) + (v.z + v.w);
#pragma unroll
    for (int d = 16; d; d >>= 1) s += __shfl_xor_sync(0xffffffffu, s, d);
    const float mu = s * (1.0f / 128.0f);
    float dx = v.x - mu, dy = v.y - mu, dz = v.z - mu, dw = v.w - mu;
    float q = (dx * dx + dy * dy) + (dz * dz + dw * dw);
#pragma unroll
    for (int d = 16; d; d >>= 1) q += __shfl_xor_sync(0xffffffffu, q, d);
    const float rstd = rsqrtf(q * (1.0f / 128.0f) + 1e-5f);
    float4 gg = ((const float4*)g)[lane];
    float4 bb = ((const float4*)bparm)[lane];
    float4 o;
    o.x = fmaf(dx * rstd, gg.x, bb.x);
    o.y = fmaf(dy * rstd, gg.y, bb.y);
    o.z = fmaf(dz * rstd, gg.z, bb.z);
    o.w = fmaf(dw * rstd, gg.w, bb.w);
    ((float4*)(g_hn + (size_t)row * Hn))[lane] = o;
}

// ---------------- row normalize k-table: kn + packed meta --------------------
__global__ void __launch_bounds__(256) norm_kernel()
{
    const int lane = threadIdx.x & 31;
    const int row  = blockIdx.x * 8 + (threadIdx.x >> 5);
    float4 v = ((const float4*)(g_kt + (size_t)row * Hn))[lane];
    float q = (v.x * v.x + v.y * v.y) + (v.z * v.z + v.w * v.w);
#pragma unroll
    for (int d = 16; d; d >>= 1) q += __shfl_xor_sync(0xffffffffu, q, d);
    const float nrm = sqrtf(q);
    const float den = fmaxf(nrm, 1e-12f);
    const float inv = 1.0f / den;
    float4 o; o.x = v.x * inv; o.y = v.y * inv; o.z = v.z * inv; o.w = v.w * inv;
    ((float4*)(g_kn + (size_t)row * Hn))[lane] = o;
    if (lane == 0) g_meta[row] = make_float2(nrm, q * inv * inv);
}

// ---------------- sequential memory-matrix scan: 1 CTA per batch -------------
// EXACTLY the R7 winner (1063.9us): 256 threads, thread=(row r=tid>>1, half
// hh=tid&1), 64 cols (32 float2) of M per thread, fused gated update+matvec
// post-barrier, kn_{t+1} preloaded pre-barrier, 4-chained-shfl energy coset
// reduce, cp.async 8-slot ring (dist 4, wait 2), halves at 68-float offsets.
#define SCAN_STEP(T, KC, KN) do {                                              \
    const int ns_ = ((T) + 1) & 7;                                             \
    float vp_ = acc + __shfl_xor_sync(0xffffffffu, acc, 1);                    \
    const float rr_ = fmaf(meta_cur.x, kv_cur, -vp_);                          \
    float e_ = rr_ * rr_;                                                      \
    e_ += __shfl_xor_sync(0xffffffffu, e_, 2);                                 \
    e_ += __shfl_xor_sync(0xffffffffu, e_, 4);                                 \
    e_ += __shfl_xor_sync(0xffffffffu, e_, 8);                                 \
    e_ += __shfl_xor_sync(0xffffffffu, e_, 16);                                \
    _Pragma("unroll")                                                          \
    for (int j_ = 0; j_ < 16; ++j_) {                                          \
        float4 v_ = *(const float4*)(s_kn[ns_] + padoff + j_ * 4);             \
        KN[2 * j_]     = make_float2(v_.x, v_.y);                              \
        KN[2 * j_ + 1] = make_float2(v_.z, v_.w);                              \
    }                                                                          \
    const float  kv_nxt_   = s_kn[ns_][kvidx];                                 \
    const float2 meta_nxt_ = s_meta[ns_];                                      \
    if (lane == 0) s_part[(T) & 1][wid] = e_;                                  \
    if (tid < 32) {                                                            \
        if ((T) + 4 < Ln) {                                                    \
            const int pb_  = ((T) + 4) & 7;                                    \
            const int tok_ = s_seq[(T) + 4];                                   \
            cp_async16(&s_kn[pb_][(tid >> 4) * 68 + (tid & 15) * 4],           \
                       g_kn + (size_t)tok_ * Hn + tid * 4);                    \
            if (tid == 0) cp_async8(&s_meta[pb_], g_meta + tok_);              \
        }                                                                      \
        asm volatile("cp.async.commit_group;" ::: "memory");                   \
        asm volatile("cp.async.wait_group 2;" ::: "memory");                   \
    }                                                                          \
    __syncthreads();                                                           \
    float4 p0_ = ((const float4*)s_part[(T) & 1])[0];                          \
    float4 p1_ = ((const float4*)s_part[(T) & 1])[1];                          \
    float tot_ = ((p0_.x + p0_.y) + (p0_.z + p0_.w))                           \
               + ((p1_.x + p1_.y) + (p1_.z + p1_.w));                          \
    float2 a0_ = make_float2(0.f, 0.f), a1_ = a0_, a2_ = a0_, a3_ = a0_;       \
    if (tot_ * meta_cur.y * (1.0f / 16384.0f) >= 0.4f) {                       \
        const float2 rr2_ = make_float2(rr_, rr_);                             \
        _Pragma("unroll")                                                      \
        for (int j_ = 0; j_ < 32; j_ += 4) {                                   \
            M2[j_ + 0] = ffma2(rr2_, KC[j_ + 0], M2[j_ + 0]);                  \
            a0_ = ffma2(M2[j_ + 0], KN[j_ + 0], a0_);                          \
            M2[j_ + 1] = ffma2(rr2_, KC[j_ + 1], M2[j_ + 1]);                  \
            a1_ = ffma2(M2[j_ + 1], KN[j_ + 1], a1_);                          \
            M2[j_ + 2] = ffma2(rr2_, KC[j_ + 2], M2[j_ + 2]);                  \
            a2_ = ffma2(M2[j_ + 2], KN[j_ + 2], a2_);                          \
            M2[j_ + 3] = ffma2(rr2_, KC[j_ + 3], M2[j_ + 3]);                  \
            a3_ = ffma2(M2[j_ + 3], KN[j_ + 3], a3_);                          \
        }                                                                      \
    } else {                                                                   \
        _Pragma("unroll")                                                      \
        for (int j_ = 0; j_ < 32; j_ += 4) {                                   \
            a0_ = ffma2(M2[j_ + 0], KN[j_ + 0], a0_);                          \
            a1_ = ffma2(M2[j_ + 1], KN[j_ + 1], a1_);                          \
            a2_ = ffma2(M2[j_ + 2], KN[j_ + 2], a2_);                          \
            a3_ = ffma2(M2[j_ + 3], KN[j_ + 3], a3_);                          \
        }                                                                      \
    }                                                                          \
    acc = ((a0_.x + a0_.y) + (a1_.x + a1_.y))                                  \
        + ((a2_.x + a2_.y) + (a3_.x + a3_.y));                                 \
    kv_cur = kv_nxt_; meta_cur = meta_nxt_;                                    \
} while (0)

__global__ void __launch_bounds__(256, 1) scan_kernel(const int* __restrict__ seq)
{
    __shared__ __align__(16) float  s_kn[8][136];   // half offset 68 (272B, 16-aligned)
    __shared__ __align__(16) float2 s_meta[8];
    __shared__ int   s_seq[Ln];
    __shared__ __align__(16) float s_part[2][8];

    const int b    = blockIdx.x;
    const int tid  = threadIdx.x;
    const int r    = tid >> 1;
    const int hh   = tid & 1;
    const int padoff = hh * 68;
    const int kvidx  = (r >> 6) * 68 + (r & 63);
    const int lane = tid & 31;
    const int wid  = tid >> 5;

    for (int i = tid; i < Ln; i += 256) s_seq[i] = seq[(size_t)b * Ln + i];

    float2 M2[32];
#pragma unroll
    for (int j = 0; j < 32; ++j) M2[j] = make_float2(0.f, 0.f);
    __syncthreads();

    // prologue: preload ring slots 0..3 (tokens 0..3), padded layout
    if (tid < 128) {
        int slot = tid >> 5, c = tid & 31;
        int tok = s_seq[slot];
        *(float4*)(s_kn[slot] + (c >> 4) * 68 + (c & 15) * 4) =
            ((const float4*)(g_kn + (size_t)tok * Hn))[c];
    }
    if (tid < 4) s_meta[tid] = g_meta[s_seq[tid]];
    __syncthreads();

    // kn_0 into ka; M=0 so acc starts at 0
    float2 ka[32], kb[32];
#pragma unroll
    for (int j = 0; j < 16; ++j) {
        float4 v = *(const float4*)(s_kn[0] + padoff + j * 4);
        ka[2 * j]     = make_float2(v.x, v.y);
        ka[2 * j + 1] = make_float2(v.z, v.w);
    }
    float  acc      = 0.f;
    float  kv_cur   = s_kn[0][kvidx];
    float2 meta_cur = s_meta[0];

    // Ln-1 = 2047 steps: 1023 pairs + 1 tail step
    for (int t = 0; t + 1 < Ln - 1; t += 2) {
        SCAN_STEP(t,     ka, kb);
        SCAN_STEP(t + 1, kb, ka);
    }
    SCAN_STEP(Ln - 2, ka, kb);   // t = 2046 (even): current=ka, next->kb

    // epilogue: acc = M_final . kn_{Ln-1}; read = (M q)_r with q = kn*norm
    {
        float vp = acc + __shfl_xor_sync(0xffffffffu, acc, 1);
        if (hh == 0) g_read[b * Hn + r] = vp * meta_cur.x;
    }
}

// ---------------- tmp = read @ rp_w^T + rp_b ---------------------------------
__global__ void __launch_bounds__(128) readrp_kernel(
    const float* __restrict__ rp_w, const float* __restrict__ rp_b)
{
    __shared__ float s_r[128];
    const int b = blockIdx.x;
    s_r[threadIdx.x] = g_read[b * Hn + threadIdx.x];
    __syncthreads();
    const int n = threadIdx.x;
    const float* wrow = rp_w + (size_t)n * Hn;
    float a0 = 0.f, a1 = 0.f, a2 = 0.f, a3 = 0.f;
#pragma unroll 8
    for (int j = 0; j < 128; j += 4) {
        a0 = fmaf(s_r[j + 0], wrow[j + 0], a0);
        a1 = fmaf(s_r[j + 1], wrow[j + 1], a1);
        a2 = fmaf(s_r[j + 2], wrow[j + 2], a2);
        a3 = fmaf(s_r[j + 3], wrow[j + 3], a3);
    }
    g_tmp[b * Hn + n] = (a0 + a1) + (a2 + a3) + rp_b[n];
}

// ---------------- logits: out[b][v] = tmp[b][:] . out_w[v][:] + out_b[v] -----
__global__ void __launch_bounds__(256) logits_kernel(
    const float* __restrict__ out_w, const float* __restrict__ out_b,
    float* __restrict__ outp)
{
    __shared__ __align__(16) float s_t[128][64];  // [j][b]
    for (int i = threadIdx.x; i < Bn * Hn; i += 256) {
        int b = i >> 7, j = i & 127;
        s_t[j][b] = g_tmp[i];
    }
    __syncthreads();

    const int v = blockIdx.x * 256 + threadIdx.x;
    const float4* wr = (const float4*)(out_w + (size_t)v * Hn);
    const float ob = out_b[v];
    float4 acc[16];
#pragma unroll
    for (int q = 0; q < 16; ++q) acc[q] = make_float4(ob, ob, ob, ob);

    for (int j4 = 0; j4 < 32; ++j4) {
        float4 w = wr[j4];
        float wj[4] = {w.x, w.y, w.z, w.w};
#pragma unroll
        for (int c = 0; c < 4; ++c) {
            const float4* tp = (const float4*)s_t[j4 * 4 + c];
#pragma unroll
            for (int q = 0; q < 16; ++q) {
                float4 t = tp[q];
                acc[q].x = fmaf(wj[c], t.x, acc[q].x);
                acc[q].y = fmaf(wj[c], t.y, acc[q].y);
                acc[q].z = fmaf(wj[c], t.z, acc[q].z);
                acc[q].w = fmaf(wj[c], t.w, acc[q].w);
            }
        }
    }
#pragma unroll
    for (int q = 0; q < 16; ++q) {
        outp[(size_t)(q * 4 + 0) * Vn + v] = acc[q].x;
        outp[(size_t)(q * 4 + 1) * Vn + v] = acc[q].y;
        outp[(size_t)(q * 4 + 2) * Vn + v] = acc[q].z;
        outp[(size_t)(q * 4 + 3) * Vn + v] = acc[q].w;
    }
}

// ---------------- launch ------------------------------------------------------
extern "C" void kernel_launch(void* const* d_in, const int* in_sizes, int n_in,
                              void* d_out, int out_size)
{
    const int*   seq    = (const int*)  d_in[0];
    const float* embedW = (const float*)d_in[1];
    const float* ff_w1  = (const float*)d_in[2];
    const float* ff_b1  = (const float*)d_in[3];
    const float* ff_w2  = (const float*)d_in[4];
    const float* ff_b2  = (const float*)d_in[5];
    const float* ln_g   = (const float*)d_in[6];
    const float* ln_b   = (const float*)d_in[7];
    const float* kp_w   = (const float*)d_in[8];
    const float* rp_w   = (const float*)d_in[9];
    const float* rp_b   = (const float*)d_in[10];
    const float* out_w  = (const float*)d_in[11];
    const float* out_b  = (const float*)d_in[12];
    float* outp = (float*)d_out;

    float *p_ff1, *p_x, *p_hn, *p_kt, *p_zero;
    cudaGetSymbolAddress((void**)&p_ff1,  g_ff1);
    cudaGetSymbolAddress((void**)&p_x,    g_x);
    cudaGetSymbolAddress((void**)&p_hn,   g_hn);
    cudaGetSymbolAddress((void**)&p_kt,   g_kt);
    cudaGetSymbolAddress((void**)&p_zero, g_zero);

    // vocab-table pipeline (32000 rows instead of 131072 tokens)
    sgemm_tn<true,  false><<<dim3(Vn / 128, 2), 256>>>(embedW, ff_w1, ff_b1, nullptr, p_ff1, 256, 128);
    sgemm_tn<false, true ><<<dim3(Vn / 128, 1), 256>>>(p_ff1,  ff_w2, ff_b2, embedW,  p_x,   128, 256);
    ln_kernel  <<<Vn / 8, 256>>>(ln_g, ln_b);
    sgemm_tn<false, false><<<dim3(Vn / 128, 1), 256>>>(p_hn,   kp_w,  p_zero, nullptr, p_kt,  128, 128);
    norm_kernel<<<Vn / 8, 256>>>();

    // sequential scan, one CTA per batch, 256 threads, M in registers (R7)
    scan_kernel<<<Bn, 256>>>(seq);

    // output head
    readrp_kernel<<<Bn, 128>>>(rp_w, rp_b);
    logits_kernel<<<Vn / 256, 256>>>(out_w, out_b, outp);
}